// round 6
// baseline (speedup 1.0000x reference)
#include <cuda_runtime.h>
#include <cstdint>

// out[b,o] = concat(x, y, outer(x,y).flatten()) @ W[o,:]^T
// == GEMM C[1024,1024] = A[1024, 263168] * W^T, A generated on the fly:
//   k <  512          : A[b,k] = x[b,k]
//   512 <= k < 1024   : A[b,k] = y[b,k-512]
//   k >= 1024         : A[b,k] = x[b,(k-1024)>>9] * y[b,(k-1024)&511]
//
// 3xTF32 (A=Ah+Al, W=Wh+Wl, RNA bit-splits; C += Ah*Wh + Ah*Wl + Al*Wh) via
// mma.sync.aligned.m16n8k8.row.col.f32.tf32.tf32.f32.
//
// KEY FIX vs previous round: the tensor-core f32 accumulate rounds toward
// zero (RZ), giving a coherent ~-2e-3 bias over a 98,688-long accumulation
// chain. We bound the chain: every FLUSH=32 chunks the MMA accumulator is
// drained into a second fp32 register accumulator with ordinary RN adds,
// cutting the bias by ~sqrt(NCHUNK/FLUSH) and the chain-length factor.

namespace {

constexpr int kN1  = 512;
constexpr int kN2  = 512;
constexpr int kBS  = 1024;
constexpr int kOUT = 1024;
constexpr int kK   = kN1 + kN2 + kN1 * kN2;  // 263168

constexpr int BM = 64;
constexpr int BN = 64;
constexpr int KC = 16;
constexpr int LDSS = 20;               // padded smem row stride -> conflict-free frag reads
constexpr int NCHUNK = kK / KC;        // 16448
constexpr int FLUSH = 32;              // chunks per MMA-accumulator chain
constexpr int NBLK = NCHUNK / FLUSH;   // 514 (exact)

static_assert(NBLK * FLUSH == NCHUNK, "flush must divide chunk count");

// RNA truncation of fp32 to tf32 (19-bit): add half-ulp in bit space, mask.
__device__ __forceinline__ uint32_t tf32_rna_bits(float f) {
  uint32_t u = __float_as_uint(f);
  return (u + 0x1000u) & 0xFFFFE000u;
}

__device__ __forceinline__ void split_tf32(float v, uint32_t& hi, uint32_t& lo) {
  hi = tf32_rna_bits(v);
  float r = v - __uint_as_float(hi);   // exact (Sterbenz)
  lo = tf32_rna_bits(r);
}

__device__ __forceinline__ void mma_tf32(float c[4], const uint32_t a[4], const uint32_t b[2]) {
  asm volatile(
      "mma.sync.aligned.m16n8k8.row.col.f32.tf32.tf32.f32 "
      "{%0,%1,%2,%3}, {%4,%5,%6,%7}, {%8,%9}, {%0,%1,%2,%3};\n"
      : "+f"(c[0]), "+f"(c[1]), "+f"(c[2]), "+f"(c[3])
      : "r"(a[0]), "r"(a[1]), "r"(a[2]), "r"(a[3]), "r"(b[0]), "r"(b[1]));
}

__global__ __launch_bounds__(256, 2) void quad_bilinear_gemm(
    const float* __restrict__ x, const float* __restrict__ y,
    const float* __restrict__ W, float* __restrict__ out) {
  __shared__ __align__(16) uint32_t As_h[BM * LDSS];
  __shared__ __align__(16) uint32_t As_l[BM * LDSS];
  __shared__ __align__(16) uint32_t Ws_h[BN * LDSS];
  __shared__ __align__(16) uint32_t Ws_l[BN * LDSS];

  const int tid = threadIdx.x;
  const int b0 = blockIdx.x * BM;
  const int o0 = blockIdx.y * BN;

  // loader mapping: each thread owns one float4 (row, 4*k4) of both tiles
  const int row = tid >> 2;  // 0..63
  const int k4  = tid & 3;   // 0..3

  const float* __restrict__ xrow = x + (b0 + row) * kN1;
  const float* __restrict__ yrow = y + (b0 + row) * kN2;
  const float* __restrict__ wrow = W + (size_t)(o0 + row) * (size_t)kK + 4 * k4;

  // mma mapping: 8 warps = 2 (M) x 4 (N); warp tile 32x16 = 2x2 m16n8k8 tiles
  const int lane = tid & 31;
  const int warp = tid >> 5;
  const int wm = warp & 1;
  const int wn = warp >> 1;
  const int g = lane >> 2;  // groupID
  const int t = lane & 3;   // threadID in group

  float acc[2][2][4];  // short-chain MMA accumulator (RZ-accumulated by HW)
  float tot[2][2][4];  // long-run fp32 accumulator (RN FADD)
#pragma unroll
  for (int mi = 0; mi < 2; mi++)
#pragma unroll
    for (int ni = 0; ni < 2; ni++)
#pragma unroll
      for (int r = 0; r < 4; r++) { acc[mi][ni][r] = 0.f; tot[mi][ni][r] = 0.f; }

  // ---- prefetch chunk 0 (k0 = 0 -> x passthrough region for all lanes) ----
  float4 wv = *(const float4*)(wrow);
  float4 av = *(const float4*)(xrow + 4 * k4);
  float xs = 1.0f;

  for (int icb = 0; icb < NBLK; icb++) {
    for (int ic2 = 0; ic2 < FLUSH; ic2++) {
      const int ic = icb * FLUSH + ic2;

      // ---- split & store current chunk to smem ----
      {
        uint32_t h0, h1, h2, h3, l0, l1, l2, l3;
        split_tf32(xs * av.x, h0, l0);
        split_tf32(xs * av.y, h1, l1);
        split_tf32(xs * av.z, h2, l2);
        split_tf32(xs * av.w, h3, l3);
        *(uint4*)&As_h[row * LDSS + 4 * k4] = make_uint4(h0, h1, h2, h3);
        *(uint4*)&As_l[row * LDSS + 4 * k4] = make_uint4(l0, l1, l2, l3);

        split_tf32(wv.x, h0, l0);
        split_tf32(wv.y, h1, l1);
        split_tf32(wv.z, h2, l2);
        split_tf32(wv.w, h3, l3);
        *(uint4*)&Ws_h[row * LDSS + 4 * k4] = make_uint4(h0, h1, h2, h3);
        *(uint4*)&Ws_l[row * LDSS + 4 * k4] = make_uint4(l0, l1, l2, l3);
      }
      __syncthreads();

      // ---- prefetch next chunk (overlaps MMA phase) ----
      if (ic + 1 < NCHUNK) {
        const int k0n = (ic + 1) * KC;
        wv = *(const float4*)(wrow + k0n);
        const int k = k0n + 4 * k4;
        if (k < kN1) {
          av = *(const float4*)(xrow + k);
          xs = 1.0f;
        } else if (k < kN1 + kN2) {
          av = *(const float4*)(yrow + (k - kN1));
          xs = 1.0f;
        } else {
          const int kk = k - (kN1 + kN2);
          xs = xrow[kk >> 9];
          av = *(const float4*)(yrow + (kk & 511));
        }
      }

      // ---- MMA: 2 k-steps of 8, 3 split-products each ----
#pragma unroll
      for (int ks = 0; ks < 2; ks++) {
        uint32_t ah[2][4], al[2][4], bh[2][2], bl[2][2];
        const int c0 = ks * 8 + t;
#pragma unroll
        for (int mi = 0; mi < 2; mi++) {
          const int m0 = wm * 32 + mi * 16;
          ah[mi][0] = As_h[(m0 + g) * LDSS + c0];
          ah[mi][1] = As_h[(m0 + g + 8) * LDSS + c0];
          ah[mi][2] = As_h[(m0 + g) * LDSS + c0 + 4];
          ah[mi][3] = As_h[(m0 + g + 8) * LDSS + c0 + 4];
          al[mi][0] = As_l[(m0 + g) * LDSS + c0];
          al[mi][1] = As_l[(m0 + g + 8) * LDSS + c0];
          al[mi][2] = As_l[(m0 + g) * LDSS + c0 + 4];
          al[mi][3] = As_l[(m0 + g + 8) * LDSS + c0 + 4];
        }
#pragma unroll
        for (int ni = 0; ni < 2; ni++) {
          const int n0 = wn * 16 + ni * 8 + g;
          bh[ni][0] = Ws_h[n0 * LDSS + c0];
          bh[ni][1] = Ws_h[n0 * LDSS + c0 + 4];
          bl[ni][0] = Ws_l[n0 * LDSS + c0];
          bl[ni][1] = Ws_l[n0 * LDSS + c0 + 4];
        }
#pragma unroll
        for (int mi = 0; mi < 2; mi++)
#pragma unroll
          for (int ni = 0; ni < 2; ni++) {
            mma_tf32(acc[mi][ni], ah[mi], bh[ni]);  // hi*hi
            mma_tf32(acc[mi][ni], ah[mi], bl[ni]);  // hi*lo
            mma_tf32(acc[mi][ni], al[mi], bh[ni]);  // lo*hi
          }
      }
      __syncthreads();
    }

    // ---- flush: drain RZ-biased MMA chain into RN fp32 accumulator ----
#pragma unroll
    for (int mi = 0; mi < 2; mi++)
#pragma unroll
      for (int ni = 0; ni < 2; ni++)
#pragma unroll
        for (int r = 0; r < 4; r++) {
          tot[mi][ni][r] += acc[mi][ni][r];
          acc[mi][ni][r] = 0.f;
        }
  }

  // ---- epilogue: fragment -> gmem, each element written exactly once ----
#pragma unroll
  for (int mi = 0; mi < 2; mi++)
#pragma unroll
    for (int ni = 0; ni < 2; ni++) {
      const int r0 = b0 + wm * 32 + mi * 16 + g;
      const int c0 = o0 + wn * 16 + ni * 8 + 2 * t;
      *(float2*)(out + (size_t)r0 * kOUT + c0) =
          make_float2(tot[mi][ni][0], tot[mi][ni][1]);
      *(float2*)(out + (size_t)(r0 + 8) * kOUT + c0) =
          make_float2(tot[mi][ni][2], tot[mi][ni][3]);
    }
}

}  // namespace

extern "C" void kernel_launch(void* const* d_in, const int* in_sizes, int n_in,
                              void* d_out, int out_size) {
  (void)in_sizes; (void)n_in; (void)out_size;
  const float* x = (const float*)d_in[0];
  const float* y = (const float*)d_in[1];
  const float* W = (const float*)d_in[2];
  float* out = (float*)d_out;

  dim3 grid(kBS / BM, kOUT / BN);  // 16 x 16 = 256 CTAs
  quad_bilinear_gemm<<<grid, 256>>>(x, y, W, out);
}